// round 9
// baseline (speedup 1.0000x reference)
#include <cuda_runtime.h>
#include <cstdint>

// Problem constants
#define BB 4096
#define NN 8192
#define THREADS 256
#define VECW 4
#define CTAS_PER_ROW 4
#define CHUNK (NN / CTAS_PER_ROW)               // 2048 elements per CTA
#define ITERS (CHUNK / (THREADS * VECW))        // 2 float4 chunks per thread

#define TAU_SYN_INV 0.5f
#define TAU_MEM_INV 0.5f
#define V_TH 1.0f
#define V_RESET 0.0f
#define INHIB (-5.0f)

// Per-row winner slot: (bits(v_new) << 32) | (0xFFFFFFFF - index).
// v_new >= 1.0 for any spiked element -> high word >= 0x3F800000 iff row
// spiked. Positive-float bits are order-monotone; complemented index gives
// first-max (smallest index on ties). Zero at module load; the last-arriving
// CTA consumes and resets it, so every graph replay sees zeros.
__device__ unsigned long long g_winner[BB];
__device__ unsigned           g_count[BB];

__device__ __forceinline__ void argmax_combine(float& bv, int& bi, float ov, int oi) {
    if (ov > bv || (ov == bv && oi < bi)) { bv = ov; bi = oi; }
}

__global__ void __launch_bounds__(THREADS, 6)
lif_fused(const float* __restrict__ x,
          const float* __restrict__ v,
          const float* __restrict__ icur,
          float* __restrict__ z_out,
          float* __restrict__ v_out,
          float* __restrict__ i_out) {
    const int cta     = blockIdx.x;
    const int row     = cta >> 2;          // CTAS_PER_ROW = 4
    const int quarter = cta & 3;
    const int t       = threadIdx.x;
    const int lane    = t & 31;

    const size_t rbase = (size_t)row * NN;
    const size_t base  = rbase + (size_t)quarter * CHUNK;
    const int    goff  = quarter * CHUNK;  // index offset within the row

    const float4* __restrict__ x4 = (const float4*)(x    + base);
    const float4* __restrict__ v4 = (const float4*)(v    + base);
    const float4* __restrict__ c4 = (const float4*)(icur + base);
    float4* __restrict__ z4  = (float4*)(z_out + base);
    float4* __restrict__ io4 = (float4*)(i_out + base);
    float4* __restrict__ vo4 = (float4*)(v_out + base);

    const float NEG_INF = __int_as_float(0xff800000u);
    const float4 inhib4 = make_float4(INHIB, INHIB, INHIB, INHIB);

    float best = NEG_INF;
    int   bidx = 0x7fffffff;

    // ---- streaming pass: write i_new, z, v_out = INHIB prefill;
    //      track argmax of v_new among spiked elements ----
    #pragma unroll
    for (int k = 0; k < ITERS; k++) {
        const int q = k * THREADS + t;     // float4 index within this chunk
        float4 xv = __ldcs(x4 + q);
        float4 vv = __ldcs(v4 + q);
        float4 cv = __ldcs(c4 + q);

        __stcs(vo4 + q, inhib4);           // overlapped constant prefill

        float4 in4, zz4;
        const float* xp = &xv.x;
        const float* vp = &vv.x;
        const float* cp = &cv.x;
        float* ip = &in4.x;
        float* zp = &zz4.x;

        #pragma unroll
        for (int c = 0; c < VECW; c++) {
            float inew = cp[c] + TAU_SYN_INV * (xp[c] - cp[c]);
            float vnew = vp[c] + TAU_MEM_INV * (inew - vp[c]);
            float zc   = (vnew >= V_TH) ? 1.0f : 0.0f;
            ip[c] = inew;
            zp[c] = zc;
            if (zc > 0.0f) {
                argmax_combine(best, bidx, vnew, goff + q * VECW + c);
            }
        }
        __stcs(io4 + q, in4);
        __stcs(z4 + q, zz4);
    }

    // ---- warp argmax, one RED per spiking warp ----
    #pragma unroll
    for (int off = 16; off > 0; off >>= 1) {
        float ov = __shfl_xor_sync(0xffffffffu, best, off);
        int   oi = __shfl_xor_sync(0xffffffffu, bidx, off);
        argmax_combine(best, bidx, ov, oi);
    }
    if (lane == 0 && best >= V_TH) {
        unsigned long long packed =
            ((unsigned long long)__float_as_uint(best) << 32) |
            (unsigned long long)(0xFFFFFFFFu - (unsigned)bidx);
        atomicMax(&g_winner[row], packed);
    }

    // ---- last-CTA-per-row fix-up (threadfence-reduction pattern) ----
    // Order THIS thread's v_out/z/i stores and winner RED before the counter
    // increment below (thread 0's increment is CTA-ordered after all threads'
    // fences via __syncthreads).
    __threadfence();
    __syncthreads();

    __shared__ unsigned s_prev;
    __shared__ unsigned long long s_slot;
    if (t == 0) {
        s_prev = atomicAdd(&g_count[row], 1u);
    }
    __syncthreads();

    if (s_prev == CTAS_PER_ROW - 1) {
        // All 4 CTAs of this row have fenced their stores + REDs.
        if (t == 0) {
            __threadfence();               // acquire side
            s_slot = *(volatile unsigned long long*)&g_winner[row];
            g_winner[row] = 0ULL;          // reset for next graph replay
            g_count[row]  = 0u;
        }
        __syncthreads();

        const unsigned long long slot = s_slot;
        const unsigned vb = (unsigned)(slot >> 32);

        if (vb >= 0x3F800000u) {
            // Row spiked: winner's v_after = V_RESET = 0 (it spiked);
            // everyone else already holds INHIB from the prefill.
            if (t == 0) {
                v_out[rbase + (0xFFFFFFFFu - (unsigned)slot)] = V_RESET;
            }
        } else {
            // Rare: no spikes -> v_out = v_new. Recompute from ORIGINAL
            // inputs (bit-identical FMA chain), no cross-CTA data deps.
            for (int n = t; n < NN; n += THREADS) {
                float xv = x[rbase + n];
                float vv = v[rbase + n];
                float cv = icur[rbase + n];
                float inew = cv + TAU_SYN_INV * (xv - cv);
                v_out[rbase + n] = vv + TAU_MEM_INV * (inew - vv);
            }
        }
    }
}

extern "C" void kernel_launch(void* const* d_in, const int* in_sizes, int n_in,
                              void* d_out, int out_size) {
    const float* x = (const float*)d_in[0];
    const float* v = (const float*)d_in[1];
    const float* i = (const float*)d_in[2];

    float* out   = (float*)d_out;
    float* z_out = out;                           // [B, N]
    float* v_out = out + (size_t)BB * NN;         // [B, N]
    float* i_out = out + 2 * (size_t)BB * NN;     // [B, N]

    lif_fused<<<BB * CTAS_PER_ROW, THREADS>>>(x, v, i, z_out, v_out, i_out);
}

// round 10
// speedup vs baseline: 1.4698x; 1.4698x over previous
#include <cuda_runtime.h>
#include <cstdint>

// Problem constants
#define BB 4096
#define NN 8192
#define THREADS 256
#define VECW 4
#define CTAS_PER_ROW 4
#define CHUNK (NN / CTAS_PER_ROW)               // 2048 elements per CTA
#define ITERS (CHUNK / (THREADS * VECW))        // 2 float4 chunks per thread

#define TAU_SYN_INV 0.5f
#define TAU_MEM_INV 0.5f
#define V_TH 1.0f
#define V_RESET 0.0f
#define INHIB (-5.0f)

// Per-row winner slot: (bits(v_new) << 32) | (0xFFFFFFFF - index).
// v_new >= 1.0 for any spiked element -> high word >= 0x3F800000 iff the row
// spiked. Positive-float bits are order-monotone; complemented index gives
// first-max (smallest index wins ties). Zero at module load; phase2 resets
// after consuming, so every graph replay sees zeros.
__device__ unsigned long long g_winner[BB];

__device__ __forceinline__ void argmax_combine(float& bv, int& bi, float ov, int oi) {
    if (ov > bv || (ov == bv && oi < bi)) { bv = ov; bi = oi; }
}

// ---------------------------------------------------------------------------
// Kernel 1: barrier-free streaming pass. 4 CTAs per row. (R5 body, proven.)
//   writes i_new, z, v_out = INHIB prefill; merges per-warp argmax candidates
//   into g_winner[row] via atomicMax (no return -> REDG).
// ---------------------------------------------------------------------------
__global__ void __launch_bounds__(THREADS, 6)
lif_phase1(const float* __restrict__ x,
           const float* __restrict__ v,
           const float* __restrict__ icur,
           float* __restrict__ z_out,
           float* __restrict__ v_out,
           float* __restrict__ i_out) {
    const int cta     = blockIdx.x;
    const int row     = cta >> 2;          // CTAS_PER_ROW = 4
    const int quarter = cta & 3;
    const int t       = threadIdx.x;
    const int lane    = t & 31;

    const size_t base = (size_t)row * NN + (size_t)quarter * CHUNK;
    const int    goff = quarter * CHUNK;   // index offset within the row

    const float4* __restrict__ x4 = (const float4*)(x    + base);
    const float4* __restrict__ v4 = (const float4*)(v    + base);
    const float4* __restrict__ c4 = (const float4*)(icur + base);
    float4* __restrict__ z4  = (float4*)(z_out + base);
    float4* __restrict__ io4 = (float4*)(i_out + base);
    float4* __restrict__ vo4 = (float4*)(v_out + base);

    const float NEG_INF = __int_as_float(0xff800000u);
    const float4 inhib4 = make_float4(INHIB, INHIB, INHIB, INHIB);

    float best = NEG_INF;
    int   bidx = 0x7fffffff;

    #pragma unroll
    for (int k = 0; k < ITERS; k++) {
        const int q = k * THREADS + t;     // float4 index within this chunk
        float4 xv = __ldcs(x4 + q);
        float4 vv = __ldcs(v4 + q);
        float4 cv = __ldcs(c4 + q);

        __stcs(vo4 + q, inhib4);           // overlapped constant prefill

        float4 in4, zz4;
        const float* xp = &xv.x;
        const float* vp = &vv.x;
        const float* cp = &cv.x;
        float* ip = &in4.x;
        float* zp = &zz4.x;

        #pragma unroll
        for (int c = 0; c < VECW; c++) {
            float inew = cp[c] + TAU_SYN_INV * (xp[c] - cp[c]);
            float vnew = vp[c] + TAU_MEM_INV * (inew - vp[c]);
            float zc   = (vnew >= V_TH) ? 1.0f : 0.0f;
            ip[c] = inew;
            zp[c] = zc;
            if (zc > 0.0f) {
                argmax_combine(best, bidx, vnew, goff + q * VECW + c);
            }
        }
        __stcs(io4 + q, in4);
        __stcs(z4 + q, zz4);
    }

    // warp argmax (first-max semantics), then one RED per spiking warp
    #pragma unroll
    for (int off = 16; off > 0; off >>= 1) {
        float ov = __shfl_xor_sync(0xffffffffu, best, off);
        int   oi = __shfl_xor_sync(0xffffffffu, bidx, off);
        argmax_combine(best, bidx, ov, oi);
    }
    if (lane == 0 && best >= V_TH) {
        unsigned long long packed =
            ((unsigned long long)__float_as_uint(best) << 32) |
            (unsigned long long)(0xFFFFFFFFu - (unsigned)bidx);
        atomicMax(&g_winner[row], packed);   // result unused -> REDG
    }

    // Allow the dependent phase2 grid to begin launch setup early; its
    // cudaGridDependencySynchronize() still waits for this grid's completion
    // and memory visibility.
#if __CUDA_ARCH__ >= 900
    cudaTriggerProgrammaticLaunchCompletion();
#endif
}

// ---------------------------------------------------------------------------
// Kernel 2 (PDL): per-row fix-up. Winner spiked -> v_after(winner) = 0;
// everything else already holds INHIB. Rare no-spike row: rewrite with v_new.
// Resets the slot for the next graph replay.
// ---------------------------------------------------------------------------
__global__ void lif_phase2(const float* __restrict__ v,
                           const float* __restrict__ i_out,
                           float* __restrict__ v_out) {
#if __CUDA_ARCH__ >= 900
    cudaGridDependencySynchronize();       // phase1 stores + REDs visible
#endif
    const int row = blockIdx.x * blockDim.x + threadIdx.x;
    if (row >= BB) return;

    unsigned long long slot = g_winner[row];
    g_winner[row] = 0ULL;                  // reset for next replay

    const unsigned vb = (unsigned)(slot >> 32);
    const size_t base = (size_t)row * NN;

    if (vb >= 0x3F800000u) {               // any spike in row
        const unsigned widx = 0xFFFFFFFFu - (unsigned)slot;
        v_out[base + widx] = V_RESET;
    } else {
        // No spikes: v_out = v_new (no resets, no inhibition). Rare; scalar ok.
        for (int n = 0; n < NN; n++) {
            float vv = v[base + n];
            float iv = i_out[base + n];
            v_out[base + n] = vv + TAU_MEM_INV * (iv - vv);
        }
    }
}

extern "C" void kernel_launch(void* const* d_in, const int* in_sizes, int n_in,
                              void* d_out, int out_size) {
    const float* x = (const float*)d_in[0];
    const float* v = (const float*)d_in[1];
    const float* i = (const float*)d_in[2];

    float* out   = (float*)d_out;
    float* z_out = out;                           // [B, N]
    float* v_out = out + (size_t)BB * NN;         // [B, N]
    float* i_out = out + 2 * (size_t)BB * NN;     // [B, N]

    lif_phase1<<<BB * CTAS_PER_ROW, THREADS>>>(x, v, i, z_out, v_out, i_out);

    // Phase 2 via Programmatic Dependent Launch: launch setup and block
    // dispatch overlap phase1's tail; cudaGridDependencySynchronize() inside
    // provides ordering + memory visibility.
    cudaLaunchAttribute attrs[1];
    attrs[0].id = cudaLaunchAttributeProgrammaticStreamSerialization;
    attrs[0].val.programmaticStreamSerializationAllowed = 1;

    cudaLaunchConfig_t cfg = {};
    cfg.gridDim  = dim3(BB / 256, 1, 1);
    cfg.blockDim = dim3(256, 1, 1);
    cfg.dynamicSmemBytes = 0;
    cfg.stream   = 0;                      // capture stream (legacy default)
    cfg.attrs    = attrs;
    cfg.numAttrs = 1;

    cudaLaunchKernelEx(&cfg, lif_phase2, v, i_out, v_out);
}